// round 2
// baseline (speedup 1.0000x reference)
#include <cuda_runtime.h>

#define BD 4
#define TD 32
#define HD 224
#define WD 224
#define CD 3
#define NPIXELS (BD*TD*HD*WD)   // 6,422,528
#define N1 79                   // int(6422528*0.2*0.8 // 13005)
#define N2 9                    // int(6422528*0.2*0.1 // 13005)
#define NBOX (N1 + 2*N2)        // 97

// scratch (allocation-free rule: __device__ globals)
__device__ unsigned char g_flags[NPIXELS];   // bit0 = R1, bit1 = R2
__device__ float         g_rtok[4];          // random token [C]

__global__ void raster_kernel(const int* __restrict__ b, const int* __restrict__ t,
                              const int* __restrict__ h, const int* __restrict__ w,
                              const int* __restrict__ rb, const int* __restrict__ rt,
                              const int* __restrict__ rh, const int* __restrict__ rw,
                              const float* __restrict__ frames,
                              float* __restrict__ M_out) {
    int box = blockIdx.x;

    // gather random_token once
    if (box == 0 && threadIdx.x < CD) {
        long long ridx = ((((long long)rb[0] * TD + rt[0]) * HD + rh[0]) * WD + rw[0]) * CD;
        g_rtok[threadIdx.x] = frames[ridx + threadIdx.x];
    }

    int bi = b[box], ti = t[box], hi0 = h[box], wi = w[box];
    int tlo = max(ti - 2, 0),   thi = min(ti + 2, TD - 1);
    int hlo = max(hi0 - 25, 0), hhi = min(hi0 + 25, HD - 1);
    int wlo = max(wi - 25, 0),  whi = min(wi + 25, WD - 1);

    // visibility mask M[b,t] — all 97 boxes contribute (hw footprint is never empty)
    if (threadIdx.x == 0) {
        for (int tt = tlo; tt < thi; tt++) M_out[bi * TD + tt] = 1.0f;
    }

    if (box >= N1 + N2) return;  // R3: affects M only
    unsigned int bit = (box < N1) ? 1u : 2u;

    int nh = hhi - hlo;
    int nt = thi - tlo;
    int nrows = nt * nh;
    for (int r = threadIdx.x; r < nrows; r += blockDim.x) {
        int tt = tlo + r / nh;
        int hh = hlo + r % nh;
        int base = ((bi * TD + tt) * HD + hh) * WD;
        int p0 = base + wlo, p1 = base + whi;       // pixel range [p0, p1)
        int w0 = p0 >> 2, w1 = (p1 + 3) >> 2;       // covering words
        for (int wd = w0; wd < w1; wd++) {
            unsigned int m = 0;
            #pragma unroll
            for (int by = 0; by < 4; by++) {
                int p = (wd << 2) + by;
                if (p >= p0 && p < p1) m |= bit << (by * 8);
            }
            atomicOr(reinterpret_cast<unsigned int*>(g_flags) + wd, m);
        }
    }
}

// each thread: 4 pixels = 12 floats = 3 float4, + 1 uint of flags
__global__ void apply_kernel(const float* __restrict__ frames,
                             const float* __restrict__ mask_token,
                             float* __restrict__ out) {
    int i = blockIdx.x * blockDim.x + threadIdx.x;
    if (i >= NPIXELS / 4) return;

    unsigned int f4 = reinterpret_cast<const unsigned int*>(g_flags)[i];
    const float4* src = reinterpret_cast<const float4*>(frames) + (size_t)i * 3;
    float4* dst = reinterpret_cast<float4*>(out) + (size_t)i * 3;

    float4 a = src[0], bq = src[1], c = src[2];

    if (f4 != 0u) {
        float mt0 = __ldg(mask_token + 0), mt1 = __ldg(mask_token + 1), mt2 = __ldg(mask_token + 2);
        float rt0 = g_rtok[0], rt1 = g_rtok[1], rt2 = g_rtok[2];

        float v[12];
        v[0]=a.x;  v[1]=a.y;  v[2]=a.z;  v[3]=a.w;
        v[4]=bq.x; v[5]=bq.y; v[6]=bq.z; v[7]=bq.w;
        v[8]=c.x;  v[9]=c.y;  v[10]=c.z; v[11]=c.w;

        #pragma unroll
        for (int p = 0; p < 4; p++) {
            unsigned int fl = (f4 >> (p * 8)) & 0xFFu;
            if (fl) {
                bool r2 = (fl & 2u) != 0u;   // R2 wins over R1
                v[p*3 + 0] = r2 ? rt0 : mt0;
                v[p*3 + 1] = r2 ? rt1 : mt1;
                v[p*3 + 2] = r2 ? rt2 : mt2;
            }
        }

        a.x=v[0];  a.y=v[1];  a.z=v[2];  a.w=v[3];
        bq.x=v[4]; bq.y=v[5]; bq.z=v[6]; bq.w=v[7];
        c.x=v[8];  c.y=v[9];  c.z=v[10]; c.w=v[11];
    }

    dst[0] = a; dst[1] = bq; dst[2] = c;
}

extern "C" void kernel_launch(void* const* d_in, const int* in_sizes, int n_in,
                              void* d_out, int out_size) {
    const float* frames     = (const float*)d_in[0];
    const float* mask_token = (const float*)d_in[1];
    const int* b  = (const int*)d_in[2];
    const int* t  = (const int*)d_in[3];
    const int* h  = (const int*)d_in[4];
    const int* w  = (const int*)d_in[5];
    const int* rb = (const int*)d_in[6];
    const int* rt = (const int*)d_in[7];
    const int* rh = (const int*)d_in[8];
    const int* rw = (const int*)d_in[9];

    float* out = (float*)d_out;
    float* M_out = out + (size_t)NPIXELS * CD;   // 128 floats of M[b,t]

    void* flags_ptr = nullptr;
    cudaGetSymbolAddress(&flags_ptr, g_flags);

    cudaMemsetAsync(flags_ptr, 0, NPIXELS);
    cudaMemsetAsync(M_out, 0, BD * TD * sizeof(float));

    raster_kernel<<<NBOX, 256>>>(b, t, h, w, rb, rt, rh, rw, frames, M_out);

    int nthreads = NPIXELS / 4;                  // 1,605,632
    apply_kernel<<<(nthreads + 255) / 256, 256>>>(frames, mask_token, out);
}